// round 6
// baseline (speedup 1.0000x reference)
#include <cuda_runtime.h>
#include <cstdint>

#define DEVI __device__ __forceinline__

// ---------------- problem constants ----------------
constexpr int BATCH = 32;
constexpr int SEQ   = 577;
constexpr int DIMC  = 768;
constexpr int NH    = 12;
constexpr int HD    = 64;
constexpr int MROWS = BATCH * SEQ;      // 18464
constexpr int QKVC  = 3 * DIMC;         // 2304
constexpr int KTILES = 10;              // ceil(577/64)
constexpr int BST   = 584;              // padded bias stride (8-aligned float2 loads)

// ---------------- scratch (no allocation allowed -> device globals) ----------------
__device__ float g_qkv[(size_t)MROWS * QKVC];            // ~170 MB
__device__ float g_attn[(size_t)MROWS * DIMC];           // ~57 MB
__device__ float g_bias[(size_t)NH * BST * BST];         // ~16 MB

// ---------------- ptx helpers ----------------
DEVI uint32_t f2tf(float x){ uint32_t r; asm("cvt.rna.tf32.f32 %0, %1;" : "=r"(r) : "f"(x)); return r; }

DEVI void mma8(float d[4], const uint32_t a[4], uint32_t b0, uint32_t b1){
  asm volatile("mma.sync.aligned.m16n8k8.row.col.f32.tf32.tf32.f32 "
               "{%0,%1,%2,%3}, {%4,%5,%6,%7}, {%8,%9}, {%0,%1,%2,%3};\n"
               : "+f"(d[0]), "+f"(d[1]), "+f"(d[2]), "+f"(d[3])
               : "r"(a[0]), "r"(a[1]), "r"(a[2]), "r"(a[3]), "r"(b0), "r"(b1));
}

DEVI uint32_t sptr(const void* p){ return (uint32_t)__cvta_generic_to_shared(p); }

DEVI void cpa16(uint32_t s, const void* g, bool pred){
  int n = pred ? 16 : 0;
  asm volatile("cp.async.cg.shared.global [%0], [%1], 16, %2;\n" :: "r"(s), "l"(g), "r"(n));
}
DEVI void cp_commit(){ asm volatile("cp.async.commit_group;\n"); }
template<int N> DEVI void cp_wait(){ asm volatile("cp.async.wait_group %0;\n" :: "n"(N)); }

// ---------------- bias gather kernel ----------------
__global__ void bias_pre(const float* __restrict__ table, const int* __restrict__ ridx){
  const int q = blockIdx.x, h = blockIdx.y;
  for (int k = threadIdx.x; k < SEQ; k += blockDim.x){
    int idx = ridx[q * SEQ + k];
    g_bias[((size_t)h * BST + q) * BST + k] = table[idx * NH + h];
  }
}

// ---------------- TF32 GEMM: C[M,N] = A[M,K] @ B[K,N] (+bias), 3-stage cp.async ----------------
constexpr int ASTR = 36;                 // A smem stride (36 % 32 == 4 -> conflict-free frag loads)
constexpr int BSTR = 132;                // B smem stride
constexpr int ABUF = 128 * ASTR;         // 4608 floats
constexpr int BBUF = 32 * BSTR;          // 4224 floats
constexpr int STAGES = 3;
constexpr int GEMM_SMEM = STAGES * (ABUF + BBUF) * 4;   // 105984 bytes -> 2 CTAs/SM

template<bool HASB>
__global__ __launch_bounds__(256)
void gemm_tf32(const float* __restrict__ A, const float* __restrict__ Bm,
               const float* __restrict__ bias, float* __restrict__ C,
               int M, int N, int K)
{
  extern __shared__ float sm[];
  float* Asm = sm;
  float* Bsm = sm + STAGES*ABUF;

  const int tid  = threadIdx.x;
  const int warp = tid >> 5, lane = tid & 31;
  const int wm = warp >> 2, wn = warp & 3;         // 2 x 4 warp grid, warptile 64x32
  const int g = lane >> 2, tg = lane & 3;
  const int bm0 = blockIdx.y * 128;
  const int bn0 = blockIdx.x * 128;

  float acc[4][4][4];
  #pragma unroll
  for (int i=0;i<4;i++)
    #pragma unroll
    for (int j=0;j<4;j++)
      #pragma unroll
      for (int r=0;r<4;r++) acc[i][j][r] = 0.f;

  const int NT = K >> 5;

  auto issue = [&](int kt, int buf){
    const int k0 = kt << 5;
    #pragma unroll
    for (int i=0;i<4;i++){
      int lin = tid + (i<<8);
      int r = lin >> 3, c4 = (lin & 7) << 2;       // 128 rows x 8 float4
      int row = bm0 + r;
      bool p = row < M;
      const float* src = A + (size_t)(p ? row : 0) * K + (k0 + c4);
      cpa16(sptr(Asm + buf*ABUF + r*ASTR + c4), src, p);
    }
    #pragma unroll
    for (int i=0;i<4;i++){
      int lin = tid + (i<<8);
      int r = lin >> 5, c4 = (lin & 31) << 2;      // 32 rows x 32 float4
      const float* src = Bm + (size_t)(k0 + r) * N + (bn0 + c4);
      cpa16(sptr(Bsm + buf*BBUF + r*BSTR + c4), src, true);
    }
    cp_commit();
  };

  issue(0, 0);
  if (NT > 1) issue(1, 1);

  for (int kt = 0; kt < NT; kt++){
    const int buf = kt % STAGES;
    // prefetch tile kt+2 into ring slot (readers of that slot drained at iter kt-1's sync)
    if (kt + 2 < NT) issue(kt + 2, (kt + 2) % STAGES);
    // wait until group kt has landed (allow the newer groups to stay in flight)
    if      (kt + 2 < NT) cp_wait<2>();
    else if (kt + 1 < NT) cp_wait<1>();
    else                  cp_wait<0>();
    __syncthreads();

    const float* Ab = Asm + buf*ABUF;
    const float* Bb = Bsm + buf*BBUF;
    #pragma unroll
    for (int kk = 0; kk < 4; kk++){
      const int k = (kk << 3) + tg;
      uint32_t af[4][4], bf[4][2];
      #pragma unroll
      for (int mt = 0; mt < 4; mt++){
        const int m = wm*64 + mt*16 + g;
        af[mt][0] = f2tf(Ab[(m    )*ASTR + k    ]);
        af[mt][1] = f2tf(Ab[(m + 8)*ASTR + k    ]);
        af[mt][2] = f2tf(Ab[(m    )*ASTR + k + 4]);
        af[mt][3] = f2tf(Ab[(m + 8)*ASTR + k + 4]);
      }
      #pragma unroll
      for (int nt = 0; nt < 4; nt++){
        const int n = wn*32 + nt*8 + g;
        bf[nt][0] = f2tf(Bb[(k    )*BSTR + n]);
        bf[nt][1] = f2tf(Bb[(k + 4)*BSTR + n]);
      }
      #pragma unroll
      for (int mt = 0; mt < 4; mt++)
        #pragma unroll
        for (int nt = 0; nt < 4; nt++)
          mma8(acc[mt][nt], af[mt], bf[nt][0], bf[nt][1]);
    }
    __syncthreads();
  }

  // epilogue
  #pragma unroll
  for (int mt = 0; mt < 4; mt++){
    const int r0 = bm0 + wm*64 + mt*16 + g;
    const int r1 = r0 + 8;
    #pragma unroll
    for (int nt = 0; nt < 4; nt++){
      const int col = bn0 + wn*32 + nt*8 + (tg << 1);
      float b0 = 0.f, b1 = 0.f;
      if (HASB){ b0 = bias[col]; b1 = bias[col + 1]; }
      if (r0 < M){
        float2 v; v.x = acc[mt][nt][0] + b0; v.y = acc[mt][nt][1] + b1;
        *(float2*)&C[(size_t)r0 * N + col] = v;
      }
      if (r1 < M){
        float2 v; v.x = acc[mt][nt][2] + b0; v.y = acc[mt][nt][3] + b1;
        *(float2*)&C[(size_t)r1 * N + col] = v;
      }
    }
  }
}

// ---------------- fused flash attention (tf32 mma, online softmax, fused rel-pos bias) ----------------
constexpr int KS = 68;                          // smem stride, 68 % 32 == 4 -> conflict-free
constexpr int ATTN_SMEM = 3 * 64 * KS * 4;      // K tile + V tile + (Q|P) tile = 52224 B

__global__ __launch_bounds__(128)
void attn_kernel()
{
  extern __shared__ float sm[];
  float* Ksm = sm;
  float* Vsm = sm + 64*KS;
  float* QP  = sm + 2*64*KS;    // Q tile at init, per-warp P buffers afterwards

  const int qt = blockIdx.x, h = blockIdx.y, b = blockIdx.z;
  const int tid = threadIdx.x;
  const int warp = tid >> 5, lane = tid & 31;
  const int g = lane >> 2, tg = lane & 3;

  // ---- load Q tile (fp32) ----
  #pragma unroll
  for (int i = 0; i < 8; i++){
    int lin = tid + (i << 7);
    int r = lin >> 4, c4 = (lin & 15) << 2;
    int q = qt*64 + r;
    float4 v = make_float4(0.f,0.f,0.f,0.f);
    if (q < SEQ) v = *(const float4*)&g_qkv[(size_t)(b*SEQ + q)*QKVC + h*HD + c4];
    QP[r*KS + c4 + 0] = v.x; QP[r*KS + c4 + 1] = v.y;
    QP[r*KS + c4 + 2] = v.z; QP[r*KS + c4 + 3] = v.w;
  }
  __syncthreads();

  // ---- Q fragments (register-resident, tf32) ----
  uint32_t qa[8][4];
  {
    const int m = warp*16 + g;
    #pragma unroll
    for (int kk = 0; kk < 8; kk++){
      const int k = (kk << 3) + tg;
      qa[kk][0] = f2tf(QP[(m    )*KS + k    ]);
      qa[kk][1] = f2tf(QP[(m + 8)*KS + k    ]);
      qa[kk][2] = f2tf(QP[(m    )*KS + k + 4]);
      qa[kk][3] = f2tf(QP[(m + 8)*KS + k + 4]);
    }
  }
  __syncthreads();   // all warps done reading Q before QP is reused for P

  float O[8][4];
  #pragma unroll
  for (int i=0;i<8;i++){ O[i][0]=0.f; O[i][1]=0.f; O[i][2]=0.f; O[i][3]=0.f; }
  float mr0 = -1e30f, mr1 = -1e30f, lr0 = 0.f, lr1 = 0.f;

  const int r0g = qt*64 + warp*16 + g;
  const int r1g = r0g + 8;
  const size_t bofs0 = ((size_t)h*BST + r0g) * BST;
  const size_t bofs1 = ((size_t)h*BST + r1g) * BST;

  for (int kt = 0; kt < KTILES; kt++){
    __syncthreads();
    // ---- load K / V tiles, convert to tf32 at store ----
    #pragma unroll
    for (int i = 0; i < 8; i++){
      int lin = tid + (i << 7);
      int r = lin >> 4, c4 = (lin & 15) << 2;
      int krow = kt*64 + r;
      float4 kv = make_float4(0.f,0.f,0.f,0.f);
      float4 vv = make_float4(0.f,0.f,0.f,0.f);
      if (krow < SEQ){
        const float* base = &g_qkv[(size_t)(b*SEQ + krow)*QKVC + h*HD + c4];
        kv = *(const float4*)(base + DIMC);
        vv = *(const float4*)(base + 2*DIMC);
      }
      Ksm[r*KS + c4 + 0] = __uint_as_float(f2tf(kv.x));
      Ksm[r*KS + c4 + 1] = __uint_as_float(f2tf(kv.y));
      Ksm[r*KS + c4 + 2] = __uint_as_float(f2tf(kv.z));
      Ksm[r*KS + c4 + 3] = __uint_as_float(f2tf(kv.w));
      Vsm[r*KS + c4 + 0] = __uint_as_float(f2tf(vv.x));
      Vsm[r*KS + c4 + 1] = __uint_as_float(f2tf(vv.y));
      Vsm[r*KS + c4 + 2] = __uint_as_float(f2tf(vv.z));
      Vsm[r*KS + c4 + 3] = __uint_as_float(f2tf(vv.w));
    }
    __syncthreads();

    // ---- S = Q @ K^T ----
    float S[8][4];
    #pragma unroll
    for (int i=0;i<8;i++){ S[i][0]=0.f; S[i][1]=0.f; S[i][2]=0.f; S[i][3]=0.f; }
    #pragma unroll
    for (int kk = 0; kk < 8; kk++){
      const int k = (kk << 3) + tg;
      #pragma unroll
      for (int nt = 0; nt < 8; nt++){
        uint32_t kb0 = __float_as_uint(Ksm[(nt*8 + g)*KS + k    ]);
        uint32_t kb1 = __float_as_uint(Ksm[(nt*8 + g)*KS + k + 4]);
        mma8(S[nt], qa[kk], kb0, kb1);
      }
    }

    // ---- scale + relative-position bias + pad mask ----
    #pragma unroll
    for (int nt = 0; nt < 8; nt++){
      const int kc = kt*64 + nt*8 + (tg << 1);
      float b00=0.f, b01=0.f, b10=0.f, b11=0.f;
      if (kc < SEQ - 1){
        if (r0g < SEQ){ float2 t = *(const float2*)&g_bias[bofs0 + kc]; b00 = t.x; b01 = t.y; }
        if (r1g < SEQ){ float2 t = *(const float2*)&g_bias[bofs1 + kc]; b10 = t.x; b11 = t.y; }
      } else if (kc < SEQ){
        if (r0g < SEQ) b00 = g_bias[bofs0 + kc];
        if (r1g < SEQ) b10 = g_bias[bofs1 + kc];
      }
      S[nt][0] = (kc     < SEQ) ? fmaf(S[nt][0], 0.125f, b00) : -1e30f;
      S[nt][1] = (kc + 1 < SEQ) ? fmaf(S[nt][1], 0.125f, b01) : -1e30f;
      S[nt][2] = (kc     < SEQ) ? fmaf(S[nt][2], 0.125f, b10) : -1e30f;
      S[nt][3] = (kc + 1 < SEQ) ? fmaf(S[nt][3], 0.125f, b11) : -1e30f;
    }

    // ---- online softmax (rows g and g+8, quad shuffles) ----
    float mx0 = -1e30f, mx1 = -1e30f;
    #pragma unroll
    for (int nt = 0; nt < 8; nt++){
      mx0 = fmaxf(mx0, fmaxf(S[nt][0], S[nt][1]));
      mx1 = fmaxf(mx1, fmaxf(S[nt][2], S[nt][3]));
    }
    mx0 = fmaxf(mx0, __shfl_xor_sync(0xffffffffu, mx0, 1));
    mx0 = fmaxf(mx0, __shfl_xor_sync(0xffffffffu, mx0, 2));
    mx1 = fmaxf(mx1, __shfl_xor_sync(0xffffffffu, mx1, 1));
    mx1 = fmaxf(mx1, __shfl_xor_sync(0xffffffffu, mx1, 2));

    const float mn0 = fmaxf(mr0, mx0), mn1 = fmaxf(mr1, mx1);
    const float a0 = __expf(mr0 - mn0), a1 = __expf(mr1 - mn1);
    mr0 = mn0; mr1 = mn1;

    float s0 = 0.f, s1 = 0.f;
    #pragma unroll
    for (int nt = 0; nt < 8; nt++){
      S[nt][0] = __expf(S[nt][0] - mn0);
      S[nt][1] = __expf(S[nt][1] - mn0);
      S[nt][2] = __expf(S[nt][2] - mn1);
      S[nt][3] = __expf(S[nt][3] - mn1);
      s0 += S[nt][0] + S[nt][1];
      s1 += S[nt][2] + S[nt][3];
    }
    s0 += __shfl_xor_sync(0xffffffffu, s0, 1);
    s0 += __shfl_xor_sync(0xffffffffu, s0, 2);
    s1 += __shfl_xor_sync(0xffffffffu, s1, 1);
    s1 += __shfl_xor_sync(0xffffffffu, s1, 2);
    lr0 = lr0*a0 + s0;
    lr1 = lr1*a1 + s1;
    #pragma unroll
    for (int dt = 0; dt < 8; dt++){ O[dt][0]*=a0; O[dt][1]*=a0; O[dt][2]*=a1; O[dt][3]*=a1; }

    // ---- P -> per-warp smem (C-layout -> A-layout round trip) ----
    const int m = warp*16 + g;
    #pragma unroll
    for (int nt = 0; nt < 8; nt++){
      const int c = nt*8 + (tg << 1);
      float2 v0; v0.x = __uint_as_float(f2tf(S[nt][0])); v0.y = __uint_as_float(f2tf(S[nt][1]));
      *(float2*)&QP[(m    )*KS + c] = v0;
      float2 v1; v1.x = __uint_as_float(f2tf(S[nt][2])); v1.y = __uint_as_float(f2tf(S[nt][3]));
      *(float2*)&QP[(m + 8)*KS + c] = v1;
    }
    __syncwarp();

    // ---- O += P @ V ----
    #pragma unroll
    for (int kk = 0; kk < 8; kk++){
      const int k = (kk << 3) + tg;
      uint32_t pa[4];
      pa[0] = __float_as_uint(QP[(m    )*KS + k    ]);
      pa[1] = __float_as_uint(QP[(m + 8)*KS + k    ]);
      pa[2] = __float_as_uint(QP[(m    )*KS + k + 4]);
      pa[3] = __float_as_uint(QP[(m + 8)*KS + k + 4]);
      #pragma unroll
      for (int dt = 0; dt < 8; dt++){
        uint32_t vb0 = __float_as_uint(Vsm[(k    )*KS + dt*8 + g]);
        uint32_t vb1 = __float_as_uint(Vsm[(k + 4)*KS + dt*8 + g]);
        mma8(O[dt], pa, vb0, vb1);
      }
    }
  }

  // ---- epilogue: normalize + write [B, N, h*64+d] ----
  const float i0 = 1.f / lr0, i1 = 1.f / lr1;
  #pragma unroll
  for (int dt = 0; dt < 8; dt++){
    const int col = h*HD + dt*8 + (tg << 1);
    if (r0g < SEQ){
      float2 v; v.x = O[dt][0]*i0; v.y = O[dt][1]*i0;
      *(float2*)&g_attn[(size_t)(b*SEQ + r0g)*DIMC + col] = v;
    }
    if (r1g < SEQ){
      float2 v; v.x = O[dt][2]*i1; v.y = O[dt][3]*i1;
      *(float2*)&g_attn[(size_t)(b*SEQ + r1g)*DIMC + col] = v;
    }
  }
}

// ---------------- launch ----------------
extern "C" void kernel_launch(void* const* d_in, const int* in_sizes, int n_in,
                              void* d_out, int out_size)
{
  const float* x      = (const float*)d_in[0];
  const float* qkv_w  = (const float*)d_in[1];
  const float* table  = (const float*)d_in[2];
  const float* proj_w = (const float*)d_in[3];
  const float* proj_b = (const float*)d_in[4];
  const int*   ridx   = (const int*)d_in[5];
  float* out = (float*)d_out;

  float *qkv_p = nullptr, *attn_p = nullptr;
  cudaGetSymbolAddress((void**)&qkv_p,  g_qkv);
  cudaGetSymbolAddress((void**)&attn_p, g_attn);

  cudaFuncSetAttribute((const void*)gemm_tf32<false>, cudaFuncAttributeMaxDynamicSharedMemorySize, GEMM_SMEM);
  cudaFuncSetAttribute((const void*)gemm_tf32<true>,  cudaFuncAttributeMaxDynamicSharedMemorySize, GEMM_SMEM);
  cudaFuncSetAttribute((const void*)attn_kernel,      cudaFuncAttributeMaxDynamicSharedMemorySize, ATTN_SMEM);

  // 1) gather relative-position bias into [12][584][584]
  bias_pre<<<dim3(SEQ, NH), 128>>>(table, ridx);

  // 2) QKV GEMM: [18464,768] @ [768,2304]
  gemm_tf32<false><<<dim3(QKVC/128, (MROWS + 127)/128), 256, GEMM_SMEM>>>(
      x, qkv_w, nullptr, qkv_p, MROWS, QKVC, DIMC);

  // 3) fused attention (flash-style, bias fused)
  attn_kernel<<<dim3(KTILES, NH, BATCH), 128, ATTN_SMEM>>>();

  // 4) proj GEMM + bias: [18464,768] @ [768,768]
  gemm_tf32<true><<<dim3(DIMC/128, (MROWS + 127)/128), 256, GEMM_SMEM>>>(
      attn_p, proj_w, proj_b, out, MROWS, DIMC, DIMC);
}